// round 17
// baseline (speedup 1.0000x reference)
#include <cuda_runtime.h>
#include <cuda_bf16.h>

#define NUM_O 1024
#define THREADS 256            // each thread owns 4 output columns: o = tid*4
#define RPT 4                  // rows per tile
#define BLOCKS_PER_SM 4
#define GRID_BLOCKS (148 * BLOCKS_PER_SM)

__device__ __forceinline__ float ex2_(float x) {
    float y; asm("ex2.approx.ftz.f32 %0, %1;" : "=f"(y) : "f"(x)); return y;
}
__device__ __forceinline__ float rcp_(float x) {
    float y; asm("rcp.approx.ftz.f32 %0, %1;" : "=f"(y) : "f"(x)); return y;
}

// 4-coeff uniform-sigma fast path (verified R3-R16, rel_err ~2.6e-6):
//   c = exp(-2*ls)*log2e ; sg = -c*|mu|^2 ; s_k = c*(2*mu_k - 1) ; scx = -c
//   arg_true = sg + s0*x0+s1*x1+s2*x2 + scx*(xx-(x0+x1+x2))
// UNI: scx term is per-row constant -> cancels in normalization; remaining
// arg <= 0 for x,mu in [0,1]^3 (no overflow).
template<bool UNI>
__device__ __forceinline__ void run_tiles(
    float4 G, float4 A, float4 B, float4 C, float4 S,
    float4 (*xs)[RPT], float (*wsum)[8],
    const float* __restrict__ x, float* __restrict__ out,
    int rows, int tiles, int tid, int warp, int lane)
{
    const int xmax = rows * 3 - 1;
    int buf = 0;

    // Preload first tile's x into smem buffer 0 (padded: row r -> float4).
    if (tid < RPT * 4) {
        const int r = tid >> 2, c = tid & 3;
        int idx = blockIdx.x * (RPT * 3) + r * 3 + c;
        reinterpret_cast<float*>(&xs[0][r])[c] =
            (c < 3) ? __ldg(&x[idx <= xmax ? idx : xmax]) : 0.0f;
    }
    __syncthreads();

    for (int t = blockIdx.x; t < tiles; t += GRID_BLOCKS, buf ^= 1) {
        const int rbase = t * RPT;

        float e[RPT][4];
        float acc[RPT];

        #pragma unroll
        for (int r = 0; r < RPT; r++) {
            const float4 xr = xs[buf][r];     // one LDS.128 broadcast per row
            const float x0 = xr.x, x1 = xr.y, x2 = xr.z;

            float b0 = G.x, b1 = G.y, b2 = G.z, b3 = G.w;
            if (!UNI) {
                float sxm = (x0*x0 + x1*x1 + x2*x2) - (x0 + x1 + x2);
                b0 = fmaf(S.x, sxm, b0); b1 = fmaf(S.y, sxm, b1);
                b2 = fmaf(S.z, sxm, b2); b3 = fmaf(S.w, sxm, b3);
            }
            b0 = fmaf(C.x, x2, b0); b1 = fmaf(C.y, x2, b1);
            b2 = fmaf(C.z, x2, b2); b3 = fmaf(C.w, x2, b3);
            b0 = fmaf(B.x, x1, b0); b1 = fmaf(B.y, x1, b1);
            b2 = fmaf(B.z, x1, b2); b3 = fmaf(B.w, x1, b3);
            b0 = fmaf(A.x, x0, b0); b1 = fmaf(A.y, x0, b1);
            b2 = fmaf(A.z, x0, b2); b3 = fmaf(A.w, x0, b3);

            const float v0 = ex2_(b0), v1 = ex2_(b1), v2 = ex2_(b2), v3 = ex2_(b3);
            e[r][0] = v0; e[r][1] = v1; e[r][2] = v2; e[r][3] = v3;
            acc[r] = (v0 + v1) + (v2 + v3);
        }

        // Stage 1: folded butterfly. xor16 folds 4 rows -> 2, xor8 -> 1;
        // lane l then holds row (l>>3)&3's partial over its 8-lane segment;
        // 3 plain stages finish. Lane 8r ends with row r's warp total.
        #pragma unroll
        for (int r = 0; r < 2; r++) {
            const bool hi = (lane & 16);
            const float keep = hi ? acc[r+2] : acc[r];
            const float send = hi ? acc[r]   : acc[r+2];
            acc[r] = keep + __shfl_xor_sync(0xFFFFFFFFu, send, 16);
        }
        {
            const bool hi = (lane & 8);
            const float keep = hi ? acc[1] : acc[0];
            const float send = hi ? acc[0] : acc[1];
            acc[0] = keep + __shfl_xor_sync(0xFFFFFFFFu, send, 8);
        }
        acc[0] += __shfl_xor_sync(0xFFFFFFFFu, acc[0], 4);
        acc[0] += __shfl_xor_sync(0xFFFFFFFFu, acc[0], 2);
        acc[0] += __shfl_xor_sync(0xFFFFFFFFu, acc[0], 1);
        if ((lane & 7) == 0) wsum[lane >> 3][warp] = acc[0];

        // Prefetch next tile's x into the other buffer (overlaps barrier).
        if (tid < RPT * 4) {
            const int r = tid >> 2, c = tid & 3;
            int idx = (t + GRID_BLOCKS) * (RPT * 3) + r * 3 + c;
            reinterpret_cast<float*>(&xs[buf ^ 1][r])[c] =
                (c < 3) ? __ldg(&x[idx <= xmax ? idx : xmax]) : 0.0f;
        }
        __syncthreads();   // wsum visible (the ONLY barrier per tile)

        // Stage 2: every warp self-serves. lane reads wsum[lane>>3][lane&7];
        // 3-stage xor within the 8-lane segment -> row total in all 8 lanes.
        float rr[RPT];
        {
            float p = wsum[lane >> 3][lane & 7];
            p += __shfl_xor_sync(0xFFFFFFFFu, p, 1);
            p += __shfl_xor_sync(0xFFFFFFFFu, p, 2);
            p += __shfl_xor_sync(0xFFFFFFFFu, p, 4);
            const float rc = rcp_(p);          // lane holds rcp(row lane>>3)
            #pragma unroll
            for (int r = 0; r < RPT; r++)
                rr[r] = __shfl_sync(0xFFFFFFFFu, rc, r << 3);
        }

        // Normalize + store (each thread: 1 float4 per row).
        float* orow = out + (size_t)rbase * NUM_O + tid * 4;
        const bool full = (rbase + RPT <= rows);
        #pragma unroll
        for (int r = 0; r < RPT; r++, orow += NUM_O) {
            if (!full && rbase + r >= rows) break;
            float4 v;
            v.x = e[r][0] * rr[r]; v.y = e[r][1] * rr[r];
            v.z = e[r][2] * rr[r]; v.w = e[r][3] * rr[r];
            *reinterpret_cast<float4*>(orow) = v;
        }
    }
}

__global__ void __launch_bounds__(THREADS, BLOCKS_PER_SM)
gaussian_rbf_kernel(const float* __restrict__ x,
                    const float* __restrict__ mus,
                    const float* __restrict__ log_sigmas,
                    float* __restrict__ out,
                    int rows)
{
    __shared__ __align__(16) float4 xs[2][RPT];
    __shared__ __align__(8) float wsum[RPT][8];

    const int tid  = threadIdx.x;
    const int warp = tid >> 5;
    const int lane = tid & 31;

    // --- Per-thread coefficients for columns o = tid*4 .. tid*4+3 (registers) ---
    const float LOG2E = 1.4426950408889634f;
    const float ls0 = __ldg(&log_sigmas[0]);

    const float4* mp = reinterpret_cast<const float4*>(mus + (size_t)tid * 12);
    float4 M0 = __ldg(mp + 0), M1 = __ldg(mp + 1), M2 = __ldg(mp + 2);
    float4 LS = __ldg(reinterpret_cast<const float4*>(log_sigmas + (size_t)tid * 4));

    bool uni = (LS.x == ls0) & (LS.y == ls0) & (LS.z == ls0) & (LS.w == ls0);
    int uall = __syncthreads_and(uni ? 1 : 0);

    float m0[4] = {M0.x, M0.w, M1.z, M2.y};
    float m1[4] = {M0.y, M1.x, M1.w, M2.z};
    float m2[4] = {M0.z, M1.y, M2.x, M2.w};
    float lsv[4] = {LS.x, LS.y, LS.z, LS.w};

    float4 G, A, B, C, S;
    float* Gp = &G.x; float* Ap = &A.x; float* Bp = &B.x;
    float* Cp = &C.x; float* Sp = &S.x;
    #pragma unroll
    for (int k = 0; k < 4; k++) {
        float c = __expf(-2.0f * lsv[k]) * LOG2E;
        Gp[k] = -c * (m0[k]*m0[k] + m1[k]*m1[k] + m2[k]*m2[k]);
        Ap[k] = c * (2.0f * m0[k] - 1.0f);
        Bp[k] = c * (2.0f * m1[k] - 1.0f);
        Cp[k] = c * (2.0f * m2[k] - 1.0f);
        Sp[k] = -c;
    }

    const int tiles = (rows + RPT - 1) / RPT;

    if (uall)
        run_tiles<true >(G, A, B, C, S, xs, wsum, x, out, rows, tiles, tid, warp, lane);
    else
        run_tiles<false>(G, A, B, C, S, xs, wsum, x, out, rows, tiles, tid, warp, lane);
}

extern "C" void kernel_launch(void* const* d_in, const int* in_sizes, int n_in,
                              void* d_out, int out_size) {
    const float* x          = (const float*)d_in[0];  // (B,S,3)
    const float* mus        = (const float*)d_in[1];  // (1024,3)
    const float* log_sigmas = (const float*)d_in[2];  // (1024,)
    float* out = (float*)d_out;

    const int rows = in_sizes[0] / 3;  // B*S
    gaussian_rbf_kernel<<<GRID_BLOCKS, THREADS>>>(x, mus, log_sigmas, out, rows);
}